// round 9
// baseline (speedup 1.0000x reference)
#include <cuda_runtime.h>
#include <cuda_fp16.h>
#include <math.h>

// ---------------------------------------------------------------------------
// MoE Router via 3xFP16-split mma.sync m16n8k16 GEMM (scaled lo-planes to
// dodge fp16 subnormals; chunked accumulators to kill HMMA truncation bias)
// + fused softmax/top-2 epilogue.
// BLK_T=64, grid=256, 2 CTAs/SM for latency hiding via independent barriers.
// logits = X[16384,2048] @ W[64,2048]^T + b ; softmax; top-2; renorm; one-hot.
// Output (fp32 flattened): logits | weights | selected(as float) | mask
// ---------------------------------------------------------------------------

#define T_TOKENS 16384
#define K_DIM    2048
#define E_DIM    64
#define BLK_T    64
#define KC       64                 // K elements per chunk (8 k8-blocks)
#define NCHUNK   (K_DIM / KC)       // 32
#define THREADS  256

#define OFF_W    (T_TOKENS * E_DIM)
#define OFF_SEL  (OFF_W + T_TOKENS * 2)
#define OFF_MASK (OFF_SEL + T_TOKENS * 2)

// ---- SMEM: per buffer: Ah | Al | Bh | Bl (k8-block layout, 16B pad/block)
#define ABLK   1040                 // 64 rows * 16B + 16B pad
#define BBLK   1040
#define AHo    0
#define ALo    (8 * ABLK)           // 8320
#define BHo    (2 * 8 * ABLK)       // 16640
#define BLo    (BHo + 8 * BBLK)     // 24960
#define BUFSZ  (BHo + 2 * 8 * BBLK) // 33280
#define SBIAS  (2 * BUFSZ)          // 66560
#define SMEM_TOTAL (SBIAS + 256)    // 66816
// epilogue logits scratch (64 x 65 fp32 = 16640B) aliases buffer 0

#define LO_SCALE   2048.0f
#define LO_UNSCALE 4.8828125e-4f    // 1/2048

static __device__ unsigned g_Wp[E_DIM * K_DIM];   // packed: lo16=h, hi16=l*2048

__device__ __forceinline__ void mma16(float* c, const unsigned* a, const unsigned* b) {
    asm("mma.sync.aligned.m16n8k16.row.col.f32.f16.f16.f32 "
        "{%0,%1,%2,%3}, {%4,%5,%6,%7}, {%8,%9}, {%0,%1,%2,%3};"
        : "+f"(c[0]), "+f"(c[1]), "+f"(c[2]), "+f"(c[3])
        : "r"(a[0]), "r"(a[1]), "r"(a[2]), "r"(a[3]), "r"(b[0]), "r"(b[1]));
}
__device__ __forceinline__ void mma16z(float* c, const unsigned* a, const unsigned* b) {
    asm("mma.sync.aligned.m16n8k16.row.col.f32.f16.f16.f32 "
        "{%0,%1,%2,%3}, {%4,%5,%6,%7}, {%8,%9}, {%10,%10,%10,%10};"
        : "=f"(c[0]), "=f"(c[1]), "=f"(c[2]), "=f"(c[3])
        : "r"(a[0]), "r"(a[1]), "r"(a[2]), "r"(a[3]), "r"(b[0]), "r"(b[1]),
          "f"(0.0f));
}
__device__ __forceinline__ void sts64(char* p, unsigned a, unsigned b) {
    asm volatile("st.shared.v2.b32 [%0], {%1,%2};"
                 :: "l"(p), "r"(a), "r"(b) : "memory");
}
__device__ __forceinline__ unsigned pack_h2(float x, float y) {
    __half2 h = __halves2half2(__float2half_rn(x), __float2half_rn(y));
    return *(unsigned*)&h;
}

// ---------------- W split pre-kernel ----------------
__global__ void wsplit_kernel(const float* __restrict__ W) {
    int i = blockIdx.x * 256 + threadIdx.x;
    float w = W[i];
    __half h = __float2half_rn(w);
    __half l = __float2half_rn((w - __half2float(h)) * LO_SCALE);
    g_Wp[i] = (unsigned)__half_as_ushort(h) | ((unsigned)__half_as_ushort(l) << 16);
}

// ---------------- main kernel ----------------
__global__ __launch_bounds__(THREADS, 2)
void moe_mma_kernel(const float* __restrict__ X,
                    const float* __restrict__ bias,
                    float* __restrict__ out)
{
    extern __shared__ char sm[];
    const int tid  = threadIdx.x;
    const int wid  = tid >> 5;
    const int lane = tid & 31;
    const int g    = lane >> 2;
    const int tg   = lane & 3;
    const int t0   = blockIdx.x * BLK_T;
    const int RB   = (wid >> 2) * 32;   // 2 row groups (64 tokens)
    const int CB   = (wid & 3) * 16;    // 4 col groups (64 experts)

    if (tid < E_DIM) ((float*)(sm + SBIAS))[tid] = bias[tid];

    const float4* X4  = (const float4*)X;
    const uint4*  Wp4 = (const uint4*)g_Wp;

    float acc[2][2][4];
#pragma unroll
    for (int mi = 0; mi < 2; ++mi)
#pragma unroll
        for (int ni = 0; ni < 2; ++ni)
#pragma unroll
            for (int q = 0; q < 4; ++q) acc[mi][ni][q] = 0.f;

    float4 xr[4];
    uint4  wr[4];

    // element mapping (64 rows x 16 float4 per chunk, 256 threads -> 4 each)
#define EROW    (tid >> 2)
#define EJ(q)   ((tid & 3) | ((q) << 2))

#define LDGX(C) do {                                                           \
    _Pragma("unroll")                                                          \
    for (int q = 0; q < 4; ++q)                                                \
        xr[q] = X4[(size_t)(t0 + EROW) * (K_DIM / 4) + (C) * 16 + EJ(q)];      \
    } while (0)

#define LDGW(C) do {                                                           \
    _Pragma("unroll")                                                          \
    for (int q = 0; q < 4; ++q)                                                \
        wr[q] = Wp4[(size_t)EROW * (K_DIM / 4) + (C) * 16 + EJ(q)];            \
    } while (0)

#define STAGE(P) do {                                                          \
    char* bb = sm + (P) * BUFSZ;                                               \
    _Pragma("unroll")                                                          \
    for (int q = 0; q < 4; ++q) {                                              \
        const int row = EROW, j = EJ(q);                                       \
        const int off = (j >> 1) * ABLK + row * 16 + (j & 1) * 8;              \
        float4 v = xr[q];                                                      \
        float hx = __half2float(__float2half_rn(v.x));                         \
        float hy = __half2float(__float2half_rn(v.y));                         \
        float hz = __half2float(__float2half_rn(v.z));                         \
        float hw = __half2float(__float2half_rn(v.w));                         \
        sts64(bb + AHo + off, pack_h2(v.x, v.y), pack_h2(v.z, v.w));           \
        sts64(bb + ALo + off,                                                  \
              pack_h2((v.x - hx) * LO_SCALE, (v.y - hy) * LO_SCALE),           \
              pack_h2((v.z - hz) * LO_SCALE, (v.w - hw) * LO_SCALE));          \
    }                                                                          \
    _Pragma("unroll")                                                          \
    for (int q = 0; q < 4; ++q) {                                              \
        const int row = EROW, j = EJ(q);                                       \
        const int off = (j >> 1) * BBLK + row * 16 + (j & 1) * 8;              \
        uint4 u = wr[q];                                                       \
        sts64(bb + BHo + off, __byte_perm(u.x, u.y, 0x5410),                   \
                              __byte_perm(u.z, u.w, 0x5410));                  \
        sts64(bb + BLo + off, __byte_perm(u.x, u.y, 0x7632),                   \
                              __byte_perm(u.z, u.w, 0x7632));                  \
    } } while (0)

    // prologue
    LDGX(0); LDGW(0);
    STAGE(0);
    LDGX(1); LDGW(1);
    __syncthreads();

    for (int c = 0; c < NCHUNK; ++c) {
        const int p = c & 1;
        if (c + 1 < NCHUNK) {
            STAGE(p ^ 1);
            if (c + 2 < NCHUNK) { LDGX(c + 2); LDGW(c + 2); }
        }
        const char* Ab = sm + p * BUFSZ;
        float cah[2][2][4], cal[2][2][4];
#pragma unroll
        for (int s = 0; s < 4; ++s) {           // 4 k16 steps per chunk
            unsigned ah[2][4], al[2][4], bh[2][2], bl[2][2];
#pragma unroll
            for (int mi = 0; mi < 2; ++mi) {
                const int ro = (RB + 16 * mi + g) * 16 + tg * 4;
                ah[mi][0] = *(const unsigned*)(Ab + AHo + (2*s)   * ABLK + ro);
                ah[mi][1] = *(const unsigned*)(Ab + AHo + (2*s)   * ABLK + ro + 128);
                ah[mi][2] = *(const unsigned*)(Ab + AHo + (2*s+1) * ABLK + ro);
                ah[mi][3] = *(const unsigned*)(Ab + AHo + (2*s+1) * ABLK + ro + 128);
                al[mi][0] = *(const unsigned*)(Ab + ALo + (2*s)   * ABLK + ro);
                al[mi][1] = *(const unsigned*)(Ab + ALo + (2*s)   * ABLK + ro + 128);
                al[mi][2] = *(const unsigned*)(Ab + ALo + (2*s+1) * ABLK + ro);
                al[mi][3] = *(const unsigned*)(Ab + ALo + (2*s+1) * ABLK + ro + 128);
            }
#pragma unroll
            for (int ni = 0; ni < 2; ++ni) {
                const int no = (CB + 8 * ni + g) * 16 + tg * 4;
                bh[ni][0] = *(const unsigned*)(Ab + BHo + (2*s)   * BBLK + no);
                bh[ni][1] = *(const unsigned*)(Ab + BHo + (2*s+1) * BBLK + no);
                bl[ni][0] = *(const unsigned*)(Ab + BLo + (2*s)   * BBLK + no);
                bl[ni][1] = *(const unsigned*)(Ab + BLo + (2*s+1) * BBLK + no);
            }
#pragma unroll
            for (int mi = 0; mi < 2; ++mi)
#pragma unroll
                for (int ni = 0; ni < 2; ++ni) {
                    if (s == 0) {
                        mma16z(cah[mi][ni], ah[mi], bh[ni]);
                        mma16z(cal[mi][ni], ah[mi], bl[ni]);
                        mma16 (cal[mi][ni], al[mi], bh[ni]);
                    } else {
                        mma16(cah[mi][ni], ah[mi], bh[ni]);
                        mma16(cal[mi][ni], ah[mi], bl[ni]);
                        mma16(cal[mi][ni], al[mi], bh[ni]);
                    }
                }
        }
        // fold chunk partials: acc += hi + lo/2048   (RN fp32 adds)
#pragma unroll
        for (int mi = 0; mi < 2; ++mi)
#pragma unroll
            for (int ni = 0; ni < 2; ++ni)
#pragma unroll
                for (int q = 0; q < 4; ++q)
                    acc[mi][ni][q] += fmaf(cal[mi][ni][q], LO_UNSCALE,
                                           cah[mi][ni][q]);
        __syncthreads();
    }

    // ---------------- epilogue: logits to gmem + smem ----------------
    float* lsm = (float*)sm;                 // 64 x 65 fp32 (aliases buf0)
    const float* bs = (const float*)(sm + SBIAS);

#pragma unroll
    for (int mi = 0; mi < 2; ++mi) {
        const int r0 = RB + 16 * mi + g;
#pragma unroll
        for (int ni = 0; ni < 2; ++ni) {
            const int col = CB + 8 * ni + 2 * tg;
            const float b0 = bs[col], b1 = bs[col + 1];
            const float v00 = acc[mi][ni][0] + b0, v01 = acc[mi][ni][1] + b1;
            const float v10 = acc[mi][ni][2] + b0, v11 = acc[mi][ni][3] + b1;
            *(float2*)(out + (size_t)(t0 + r0) * E_DIM + col)     = make_float2(v00, v01);
            *(float2*)(out + (size_t)(t0 + r0 + 8) * E_DIM + col) = make_float2(v10, v11);
            lsm[r0 * 65 + col]           = v00;
            lsm[r0 * 65 + col + 1]       = v01;
            lsm[(r0 + 8) * 65 + col]     = v10;
            lsm[(r0 + 8) * 65 + col + 1] = v11;
        }
    }
    __syncthreads();

    // ---------------- fused router: one thread per token ----------------
    if (tid < BLK_T) {
        const int tok = t0 + tid;
        const float* row = lsm + tid * 65;
        float b1 = -1e30f, b2 = -1e30f;
        int   i1 = 0,      i2 = 0;
#pragma unroll
        for (int e = 0; e < E_DIM; ++e) {
            const float v = row[e];
            if (v > b1)      { b2 = b1; i2 = i1; b1 = v; i1 = e; }
            else if (v > b2) { b2 = v; i2 = e; }
        }
        const float e2 = expf(b2 - b1);        // softmax denom cancels in renorm
        const float w1 = 1.0f / (1.0f + e2);
        out[OFF_W + 2 * tok]     = w1;
        out[OFF_W + 2 * tok + 1] = e2 * w1;
        out[OFF_SEL + 2 * tok]     = (float)i1;
        out[OFF_SEL + 2 * tok + 1] = (float)i2;

        float4* m4 = (float4*)(out + OFF_MASK + (size_t)tok * 128);
        const float4 z = make_float4(0.f, 0.f, 0.f, 0.f);
#pragma unroll
        for (int q = 0; q < 32; ++q) m4[q] = z;
        out[OFF_MASK + (size_t)tok * 128 + i1]      = 1.0f;
        out[OFF_MASK + (size_t)tok * 128 + 64 + i2] = 1.0f;
    }
}

extern "C" void kernel_launch(void* const* d_in, const int* in_sizes, int n_in,
                              void* d_out, int out_size)
{
    const float* X = (const float*)d_in[0];
    const float* W = (const float*)d_in[1];
    const float* b = (const float*)d_in[2];
    float* out = (float*)d_out;

    cudaFuncSetAttribute(moe_mma_kernel,
                         cudaFuncAttributeMaxDynamicSharedMemorySize, SMEM_TOTAL);

    wsplit_kernel<<<(E_DIM * K_DIM) / 256, 256>>>(W);
    moe_mma_kernel<<<T_TOKENS / BLK_T, THREADS, SMEM_TOTAL>>>(X, b, out);
}

// round 10
// speedup vs baseline: 1.1481x; 1.1481x over previous
#include <cuda_runtime.h>
#include <cuda_fp16.h>
#include <math.h>

// ---------------------------------------------------------------------------
// MoE Router via 3xFP16-split mma.sync m16n8k16 GEMM (scaled lo-planes to
// dodge fp16 subnormals; chunked accumulators to kill HMMA truncation bias)
// + ldmatrix fragment loads + fused softmax/top-2 epilogue.
// logits = X[16384,2048] @ W[64,2048]^T + b ; softmax; top-2; renorm; one-hot.
// Output (fp32 flattened): logits | weights | selected(as float) | mask
// ---------------------------------------------------------------------------

#define T_TOKENS 16384
#define K_DIM    2048
#define E_DIM    64
#define BLK_T    128
#define KC       64                 // K elements per chunk (8 k8-blocks)
#define NCHUNK   (K_DIM / KC)       // 32
#define THREADS  256

#define OFF_W    (T_TOKENS * E_DIM)
#define OFF_SEL  (OFF_W + T_TOKENS * 2)
#define OFF_MASK (OFF_SEL + T_TOKENS * 2)

// ---- SMEM: per buffer: Ah | Al | Bh | Bl (k8-block layout, 16B pad/block)
#define ABLK   2064                 // 128 rows * 16B + 16B pad
#define BBLK   1040                 // 64 rows * 16B + 16B pad
#define AHo    0
#define ALo    (8 * ABLK)           // 16512
#define BHo    (2 * 8 * ABLK)       // 33024
#define BLo    (BHo + 8 * BBLK)     // 41344
#define BUFSZ  (BHo + 2 * 8 * BBLK) // 49664
#define SBIAS  (2 * BUFSZ)
#define SMEM_TOTAL (SBIAS + 256)
// epilogue logits scratch (128 x 65 fp32 = 33280B) aliases buffer 0

#define LO_SCALE   2048.0f
#define LO_UNSCALE 4.8828125e-4f    // 1/2048

static __device__ unsigned g_Wp[E_DIM * K_DIM];   // packed: lo16=h, hi16=l*2048

__device__ __forceinline__ void mma16(float* c, const unsigned* a, const unsigned* b) {
    asm("mma.sync.aligned.m16n8k16.row.col.f32.f16.f16.f32 "
        "{%0,%1,%2,%3}, {%4,%5,%6,%7}, {%8,%9}, {%0,%1,%2,%3};"
        : "+f"(c[0]), "+f"(c[1]), "+f"(c[2]), "+f"(c[3])
        : "r"(a[0]), "r"(a[1]), "r"(a[2]), "r"(a[3]), "r"(b[0]), "r"(b[1]));
}
__device__ __forceinline__ void mma16z(float* c, const unsigned* a, const unsigned* b) {
    asm("mma.sync.aligned.m16n8k16.row.col.f32.f16.f16.f32 "
        "{%0,%1,%2,%3}, {%4,%5,%6,%7}, {%8,%9}, {%10,%10,%10,%10};"
        : "=f"(c[0]), "=f"(c[1]), "=f"(c[2]), "=f"(c[3])
        : "r"(a[0]), "r"(a[1]), "r"(a[2]), "r"(a[3]), "r"(b[0]), "r"(b[1]),
          "f"(0.0f));
}
__device__ __forceinline__ void ldsm4(unsigned& r0, unsigned& r1,
                                      unsigned& r2, unsigned& r3, unsigned a) {
    asm volatile("ldmatrix.sync.aligned.m8n8.x4.shared.b16 {%0,%1,%2,%3}, [%4];"
                 : "=r"(r0), "=r"(r1), "=r"(r2), "=r"(r3) : "r"(a));
}
__device__ __forceinline__ void sts64(unsigned p, unsigned a, unsigned b) {
    asm volatile("st.shared.v2.b32 [%0], {%1,%2};"
                 :: "r"(p), "r"(a), "r"(b) : "memory");
}
__device__ __forceinline__ unsigned pack_h2(float x, float y) {
    __half2 h = __halves2half2(__float2half_rn(x), __float2half_rn(y));
    return *(unsigned*)&h;
}
__device__ __forceinline__ unsigned smem_u32(const void* p) {
    unsigned a;
    asm("{ .reg .u64 t; cvta.to.shared.u64 t, %1; cvt.u32.u64 %0, t; }"
        : "=r"(a) : "l"(p));
    return a;
}

// ---------------- W split pre-kernel ----------------
__global__ void wsplit_kernel(const float* __restrict__ W) {
    int i = blockIdx.x * 256 + threadIdx.x;
    float w = W[i];
    __half h = __float2half_rn(w);
    __half l = __float2half_rn((w - __half2float(h)) * LO_SCALE);
    g_Wp[i] = (unsigned)__half_as_ushort(h) | ((unsigned)__half_as_ushort(l) << 16);
}

// ---------------- main kernel ----------------
__global__ __launch_bounds__(THREADS, 1)
void moe_mma_kernel(const float* __restrict__ X,
                    const float* __restrict__ bias,
                    float* __restrict__ out)
{
    extern __shared__ char sm[];
    const unsigned smb = smem_u32(sm);
    const int tid  = threadIdx.x;
    const int wid  = tid >> 5;
    const int lane = tid & 31;
    const int g    = lane >> 2;
    const int tg   = lane & 3;
    const int t0   = blockIdx.x * BLK_T;
    const int RB   = (wid >> 1) * 32;   // 4 row groups
    const int CB   = (wid & 1) * 32;    // 2 col groups

    if (tid < E_DIM) ((float*)(sm + SBIAS))[tid] = bias[tid];

    const float4* X4  = (const float4*)X;
    const uint4*  Wp4 = (const uint4*)g_Wp;

    // ldmatrix per-lane address components
    const unsigned blkA = (unsigned)(lane >> 4) * ABLK + (unsigned)(lane & 15) * 16;
    const unsigned blkB = (unsigned)(lane >> 4) * BBLK + (unsigned)(lane & 15) * 16;
    const unsigned aBase0 = smb + AHo + blkA + (unsigned)RB * 16;
    const unsigned bBase0 = smb + BHo + blkB + (unsigned)CB * 16;

    float acc[2][4][4];
#pragma unroll
    for (int mi = 0; mi < 2; ++mi)
#pragma unroll
        for (int ni = 0; ni < 4; ++ni)
#pragma unroll
            for (int q = 0; q < 4; ++q) acc[mi][ni][q] = 0.f;

    float4 xr[8];
    uint4  wr[4];

    // element mapping: X float4 idx -> row/j (8 rows per warp for bank spread)
#define XROW(q) ((tid >> 2) + 64 * ((q) >> 2))
#define XJ(q)   ((tid & 3) | (((q) & 3) << 2))
#define WROW    (tid >> 2)
#define WJ(q)   ((tid & 3) | (((q) & 3) << 2))

#define LDGX(C) do {                                                           \
    _Pragma("unroll")                                                          \
    for (int q = 0; q < 8; ++q)                                                \
        xr[q] = X4[(size_t)(t0 + XROW(q)) * (K_DIM / 4) + (C) * 16 + XJ(q)];   \
    } while (0)

#define LDGW(C) do {                                                           \
    _Pragma("unroll")                                                          \
    for (int q = 0; q < 4; ++q)                                                \
        wr[q] = Wp4[(size_t)WROW * (K_DIM / 4) + (C) * 16 + WJ(q)];            \
    } while (0)

#define STAGE(P) do {                                                          \
    const unsigned bb = smb + (P) * BUFSZ;                                     \
    _Pragma("unroll")                                                          \
    for (int q = 0; q < 8; ++q) {                                              \
        const int row = XROW(q), j = XJ(q);                                    \
        const unsigned off = (j >> 1) * ABLK + row * 16 + (j & 1) * 8;         \
        float4 v = xr[q];                                                      \
        float hx = __half2float(__float2half_rn(v.x));                         \
        float hy = __half2float(__float2half_rn(v.y));                         \
        float hz = __half2float(__float2half_rn(v.z));                         \
        float hw = __half2float(__float2half_rn(v.w));                         \
        sts64(bb + AHo + off, pack_h2(v.x, v.y), pack_h2(v.z, v.w));           \
        sts64(bb + ALo + off,                                                  \
              pack_h2((v.x - hx) * LO_SCALE, (v.y - hy) * LO_SCALE),           \
              pack_h2((v.z - hz) * LO_SCALE, (v.w - hw) * LO_SCALE));          \
    }                                                                          \
    _Pragma("unroll")                                                          \
    for (int q = 0; q < 4; ++q) {                                              \
        const int row = WROW, j = WJ(q);                                       \
        const unsigned off = (j >> 1) * BBLK + row * 16 + (j & 1) * 8;         \
        uint4 u = wr[q];                                                       \
        sts64(bb + BHo + off, __byte_perm(u.x, u.y, 0x5410),                   \
                              __byte_perm(u.z, u.w, 0x5410));                  \
        sts64(bb + BLo + off, __byte_perm(u.x, u.y, 0x7632),                   \
                              __byte_perm(u.z, u.w, 0x7632));                  \
    } } while (0)

    // prologue
    LDGX(0); LDGW(0);
    STAGE(0);
    LDGX(1); LDGW(1);
    __syncthreads();

    for (int c = 0; c < NCHUNK; ++c) {
        const int p = c & 1;
        if (c + 1 < NCHUNK) {
            STAGE(p ^ 1);
            if (c + 2 < NCHUNK) { LDGX(c + 2); LDGW(c + 2); }
        }
        const unsigned aB = aBase0 + p * BUFSZ;     // A hi plane base
        const unsigned bB = bBase0 + p * BUFSZ;     // B hi plane base
        float cah[2][4][4], cal[2][4][4];
#pragma unroll
        for (int s = 0; s < 4; ++s) {               // 4 k16 steps per chunk
            unsigned ah[2][4], al[2][4], bh[4][2], bl[4][2];
            const unsigned as = aB + (2 * s) * ABLK;
            const unsigned bs_ = bB + (2 * s) * BBLK;
#pragma unroll
            for (int mi = 0; mi < 2; ++mi) {
                ldsm4(ah[mi][0], ah[mi][1], ah[mi][2], ah[mi][3],
                      as + mi * 256);
                ldsm4(al[mi][0], al[mi][1], al[mi][2], al[mi][3],
                      as + ALo + mi * 256);
            }
#pragma unroll
            for (int np = 0; np < 2; ++np) {
                unsigned r0, r1, r2, r3;
                ldsm4(r0, r1, r2, r3, bs_ + np * 256);
                bh[2 * np][0] = r0; bh[2 * np][1] = r2;
                bh[2 * np + 1][0] = r1; bh[2 * np + 1][1] = r3;
                ldsm4(r0, r1, r2, r3, bs_ + (BLo - BHo) + np * 256);
                bl[2 * np][0] = r0; bl[2 * np][1] = r2;
                bl[2 * np + 1][0] = r1; bl[2 * np + 1][1] = r3;
            }
#pragma unroll
            for (int mi = 0; mi < 2; ++mi)
#pragma unroll
                for (int ni = 0; ni < 4; ++ni) {
                    if (s == 0) {
                        mma16z(cah[mi][ni], ah[mi], bh[ni]);
                        mma16z(cal[mi][ni], ah[mi], bl[ni]);
                        mma16 (cal[mi][ni], al[mi], bh[ni]);
                    } else {
                        mma16(cah[mi][ni], ah[mi], bh[ni]);
                        mma16(cal[mi][ni], ah[mi], bl[ni]);
                        mma16(cal[mi][ni], al[mi], bh[ni]);
                    }
                }
        }
        // fold chunk partials: acc += hi + lo/2048   (RN fp32 adds)
#pragma unroll
        for (int mi = 0; mi < 2; ++mi)
#pragma unroll
            for (int ni = 0; ni < 4; ++ni)
#pragma unroll
                for (int q = 0; q < 4; ++q)
                    acc[mi][ni][q] += fmaf(cal[mi][ni][q], LO_UNSCALE,
                                           cah[mi][ni][q]);
        __syncthreads();
    }

    // ---------------- epilogue: logits to gmem + smem ----------------
    float* lsm = (float*)sm;                 // 128 x 65 fp32 (aliases buf0)
    const float* bs = (const float*)(sm + SBIAS);

#pragma unroll
    for (int mi = 0; mi < 2; ++mi) {
        const int r0 = RB + 16 * mi + g;
#pragma unroll
        for (int ni = 0; ni < 4; ++ni) {
            const int col = CB + 8 * ni + 2 * tg;
            const float b0 = bs[col], b1 = bs[col + 1];
            const float v00 = acc[mi][ni][0] + b0, v01 = acc[mi][ni][1] + b1;
            const float v10 = acc[mi][ni][2] + b0, v11 = acc[mi][ni][3] + b1;
            *(float2*)(out + (size_t)(t0 + r0) * E_DIM + col)     = make_float2(v00, v01);
            *(float2*)(out + (size_t)(t0 + r0 + 8) * E_DIM + col) = make_float2(v10, v11);
            lsm[r0 * 65 + col]           = v00;
            lsm[r0 * 65 + col + 1]       = v01;
            lsm[(r0 + 8) * 65 + col]     = v10;
            lsm[(r0 + 8) * 65 + col + 1] = v11;
        }
    }
    __syncthreads();

    // ---------------- fused router: one thread per token ----------------
    if (tid < BLK_T) {
        const int tok = t0 + tid;
        const float* row = lsm + tid * 65;
        float b1 = -1e30f, b2 = -1e30f;
        int   i1 = 0,      i2 = 0;
#pragma unroll
        for (int e = 0; e < E_DIM; ++e) {
            const float v = row[e];
            if (v > b1)      { b2 = b1; i2 = i1; b1 = v; i1 = e; }
            else if (v > b2) { b2 = v; i2 = e; }
        }
        const float e2 = expf(b2 - b1);        // softmax denom cancels in renorm
        const float w1 = 1.0f / (1.0f + e2);
        out[OFF_W + 2 * tok]     = w1;
        out[OFF_W + 2 * tok + 1] = e2 * w1;
        out[OFF_SEL + 2 * tok]     = (float)i1;
        out[OFF_SEL + 2 * tok + 1] = (float)i2;

        float4* m4 = (float4*)(out + OFF_MASK + (size_t)tok * 128);
        const float4 z = make_float4(0.f, 0.f, 0.f, 0.f);
#pragma unroll
        for (int q = 0; q < 32; ++q) m4[q] = z;
        out[OFF_MASK + (size_t)tok * 128 + i1]      = 1.0f;
        out[OFF_MASK + (size_t)tok * 128 + 64 + i2] = 1.0f;
    }
}

extern "C" void kernel_launch(void* const* d_in, const int* in_sizes, int n_in,
                              void* d_out, int out_size)
{
    const float* X = (const float*)d_in[0];
    const float* W = (const float*)d_in[1];
    const float* b = (const float*)d_in[2];
    float* out = (float*)d_out;

    cudaFuncSetAttribute(moe_mma_kernel,
                         cudaFuncAttributeMaxDynamicSharedMemorySize, SMEM_TOTAL);

    wsplit_kernel<<<(E_DIM * K_DIM) / 256, 256>>>(W);
    moe_mma_kernel<<<T_TOKENS / BLK_T, THREADS, SMEM_TOTAL>>>(X, b, out);
}